// round 9
// baseline (speedup 1.0000x reference)
#include <cuda_runtime.h>
#include <math.h>

typedef unsigned long long ull;
typedef unsigned int u32;

#define MAXN_PAD 75008   // 293 blocks * 256 rows

// Global scratch (static __device__ arrays: never allocated at runtime)
__device__ float g_agg[(size_t)MAXN_PAD * 512];   // 153.6 MB
__device__ float g_h  [(size_t)MAXN_PAD * 64];    // 19.2 MB

__device__ __forceinline__ void upk2(ull v, float& x, float& y) {
    asm("mov.b64 {%0, %1}, %2;" : "=f"(x), "=f"(y) : "l"(v));
}
__device__ __forceinline__ void ffma2(ull& d, ull a, ull b) {
    asm("fma.rn.f32x2 %0, %1, %2, %0;" : "+l"(d) : "l"(a), "l"(b));
}
__device__ __forceinline__ void fadd2(ull& d, ull a) {
    asm("add.rn.f32x2 %0, %0, %1;" : "+l"(d) : "l"(a));
}
__device__ __forceinline__ u32 smem_u32(const void* p) {
    u32 a;
    asm("{ .reg .u64 t; cvta.to.shared.u64 t, %1; cvt.u32.u64 %0, t; }" : "=r"(a) : "l"(p));
    return a;
}
__device__ __forceinline__ void cp16(u32 dst, const void* src) {
    asm volatile("cp.async.cg.shared.global [%0], [%1], 16;" :: "r"(dst), "l"(src));
}
__device__ __forceinline__ void cp_commit() { asm volatile("cp.async.commit_group;"); }
__device__ __forceinline__ void cp_wait1()  { asm volatile("cp.async.wait_group 1;"); }
__device__ __forceinline__ void cp_wait0()  { asm volatile("cp.async.wait_group 0;"); }

// ---------------------------------------------------------------------------
// Aggregation: one warp per node.  agg[node][r*64+d] = sum_{e: rel_e=r} x[src_e][d]
// Batched: 8 independent LDGs in flight, then predicated adds (no data-dep
// control between load and consume batches -> MLP=8 per warp).
// ---------------------------------------------------------------------------
__global__ void __launch_bounds__(256)
agg_kernel(const float* __restrict__ xin,
           const int*   __restrict__ ptr,
           const int*   __restrict__ idx,
           const int*   __restrict__ rel,
           float*       __restrict__ agg,
           int n)
{
    const int node = (blockIdx.x * blockDim.x + threadIdx.x) >> 5;
    const int lane = threadIdx.x & 31;
    if (node >= n) return;

    ull acc[8];
    #pragma unroll
    for (int r = 0; r < 8; ++r) acc[r] = 0ull;

    const int e0 = ptr[node], e1 = ptr[node + 1];
    for (int eb = e0; eb < e1; eb += 32) {
        const int cnt = min(32, e1 - eb);
        int mi = 0, mr = -1;
        if (lane < cnt) { mi = idx[eb + lane]; mr = rel[eb + lane]; }

        for (int t = 0; t < cnt; t += 8) {
            ull v[8]; int rr[8];
            #pragma unroll
            for (int u = 0; u < 8; ++u) {
                int s = __shfl_sync(0xffffffffu, mi, t + u);
                rr[u] = (t + u < cnt) ? __shfl_sync(0xffffffffu, mr, t + u) : -1;
                v[u]  = *(const ull*)(xin + (size_t)s * 64 + 2 * lane);
            }
            #pragma unroll
            for (int u = 0; u < 8; ++u) {
                #pragma unroll
                for (int r = 0; r < 8; ++r)
                    if (rr[u] == r) fadd2(acc[r], v[u]);
            }
        }
    }

    float* arow = agg + (size_t)node * 512;
    #pragma unroll
    for (int r = 0; r < 8; ++r)
        *(ull*)(arow + r * 64 + 2 * lane) = acc[r];
}

// ---------------------------------------------------------------------------
// GEMM: out[256 x F] per block = A[256 x 512] @ W[512 x F]
//   512 threads = 16 warps. warp = (row-half, col-group):
//     half = w >> 3 (rows half*128 .. +127), cg = w & 7 (cols cg*CPW .. ).
//   lane owns rows {half*128 + lane + 32j}, j=0..3; thread tile 4 x CPW.
//   A SMEM: [2][256][64] floats, XOR swizzle c4^(row&7) (conflict-free LDS.128).
//   B SMEM: [2][32][F] k-pair-packed ull, broadcast LDS within warp.
//   acc lanes = (even-k partial, odd-k partial); summed in epilogue.
// ---------------------------------------------------------------------------
template<int F>
__global__ void __launch_bounds__(512, 1)
gemm_kernel(const float* __restrict__ A,
            const float* __restrict__ W,     // [512][F] k-major
            float*       __restrict__ out,
            int n)
{
    constexpr int CPW = F / 8;               // cols per warp: 8 or 5
    extern __shared__ float sm[];
    float* As = sm;                          // [2][16384] floats
    ull*   Bs = (ull*)(sm + 32768);          // [2][32*F] ull
    const u32 asb = smem_u32(As);

    const int tid  = threadIdx.x;
    const int lane = tid & 31;
    const int w    = tid >> 5;
    const int half = w >> 3;                 // 0,1
    const int cg   = w & 7;                  // 0..7
    const size_t row0 = (size_t)blockIdx.x * 256;

    // ---- A chunk staging (cp.async, swizzled) ------------------------------
    auto cpA = [&](int ch, int buf) {
        #pragma unroll
        for (int i = 0; i < 8; ++i) {
            int v  = tid + i * 512;           // 0..4095
            int r  = v >> 4, c4 = v & 15;
            u32 d = asb + (u32)((buf * 16384 + r * 64 + ((c4 ^ (r & 7)) << 2)) * 4);
            cp16(d, A + (row0 + r) * 512 + ch * 64 + c4 * 4);
        }
        cp_commit();
    };

    // ---- B chunk staging (k-pair pack via registers) -----------------------
    constexpr int BN = (32 * F + 511) / 512;  // per-thread B elements (4 or 3)
    float2 br[BN];
    auto ldgB = [&](int ch) {
        #pragma unroll
        for (int i = 0; i < BN; ++i) {
            int v = tid + i * 512;
            if (32 * F % 512 == 0 || v < 32 * F) {
                int kp = v / F, c = v % F;
                const float* p = W + (size_t)(ch * 64 + 2 * kp) * F + c;
                br[i].x = p[0]; br[i].y = p[F];
            }
        }
    };
    auto stsB = [&](int buf) {
        ull* bs = Bs + buf * 32 * F;
        #pragma unroll
        for (int i = 0; i < BN; ++i) {
            int v = tid + i * 512;
            if (32 * F % 512 == 0 || v < 32 * F) {
                int kp = v / F, c = v % F;
                *(float2*)(bs + kp * F + c) = br[i];
            }
        }
    };

    ull acc[4][CPW];
    #pragma unroll
    for (int j = 0; j < 4; ++j)
        #pragma unroll
        for (int c = 0; c < CPW; ++c) acc[j][c] = 0ull;

    // ---- pipeline prologue --------------------------------------------------
    cpA(0, 0);
    cpA(1, 1);
    ldgB(0); stsB(0);

    #pragma unroll 1
    for (int ch = 0; ch < 8; ++ch) {
        const int buf = ch & 1;
        if (ch < 7) ldgB(ch + 1);
        if (ch == 7) cp_wait0(); else cp_wait1();
        __syncthreads();

        const float* as = As + buf * 16384 + (half * 128 + lane) * 64;
        const ull*   bs = Bs + buf * 32 * F + cg * CPW;
        #pragma unroll
        for (int kp2 = 0; kp2 < 16; ++kp2) {
            ull b0[CPW], b1[CPW];
            #pragma unroll
            for (int c = 0; c < CPW; ++c) {
                b0[c] = bs[(2 * kp2) * F + c];
                b1[c] = bs[(2 * kp2 + 1) * F + c];
            }
            const int swoff = (kp2 ^ (lane & 7)) << 2;
            #pragma unroll
            for (int j = 0; j < 4; ++j) {
                ulonglong2 a = *(const ulonglong2*)(as + j * 2048 + swoff);
                #pragma unroll
                for (int c = 0; c < CPW; ++c) {
                    ffma2(acc[j][c], a.x, b0[c]);
                    ffma2(acc[j][c], a.y, b1[c]);
                }
            }
        }
        __syncthreads();

        if (ch < 7) stsB((ch + 1) & 1);
        if (ch < 6) cpA(ch + 2, buf);
    }

    // ---- epilogue -----------------------------------------------------------
    if (F == 64) {
        // ReLU, direct store (rows padded; out rows >= n unused)
        #pragma unroll
        for (int j = 0; j < 4; ++j) {
            size_t g = row0 + half * 128 + lane + 32 * j;
            float lo, hi; float4 o;
            upk2(acc[j][0], lo, hi); o.x = fmaxf(lo + hi, 0.f);
            upk2(acc[j][1], lo, hi); o.y = fmaxf(lo + hi, 0.f);
            upk2(acc[j][2], lo, hi); o.z = fmaxf(lo + hi, 0.f);
            upk2(acc[j][3], lo, hi); o.w = fmaxf(lo + hi, 0.f);
            *(float4*)(out + g * 64 + cg * 8) = o;
            upk2(acc[j][4], lo, hi); o.x = fmaxf(lo + hi, 0.f);
            upk2(acc[j][5], lo, hi); o.y = fmaxf(lo + hi, 0.f);
            upk2(acc[j][6], lo, hi); o.z = fmaxf(lo + hi, 0.f);
            upk2(acc[j][7], lo, hi); o.w = fmaxf(lo + hi, 0.f);
            *(float4*)(out + g * 64 + cg * 8 + 4) = o;
        }
    } else {
        // log_softmax over F=40 columns
        __syncthreads();                       // all done reading As
        float* so = As;                        // [256][41] exchange
        #pragma unroll
        for (int j = 0; j < 4; ++j)
            #pragma unroll
            for (int c = 0; c < CPW; ++c) {
                float lo, hi; upk2(acc[j][c], lo, hi);
                so[(half * 128 + lane + 32 * j) * 41 + cg * CPW + c] = lo + hi;
            }
        __syncthreads();

        if (tid < 256) {                       // row-per-thread softmax
            const int row = tid;
            float v[40];
            float m = -INFINITY;
            #pragma unroll
            for (int c = 0; c < 40; ++c) { v[c] = so[row * 41 + c]; m = fmaxf(m, v[c]); }
            float s = 0.f;
            #pragma unroll
            for (int c = 0; c < 40; ++c) s += expf(v[c] - m);
            float lse = m + logf(s);
            #pragma unroll
            for (int c = 0; c < 40; ++c) so[row * 41 + c] = v[c] - lse;
        }
        __syncthreads();

        // coalesced copy-out with n-guard
        const int total = (int)min((size_t)256, (size_t)n - row0) * 40;
        for (int e = tid; e < total; e += 512) {
            int r = e / 40, c = e % 40;
            out[row0 * 40 + e] = so[r * 41 + c];
        }
    }
}

// ---------------------------------------------------------------------------
extern "C" void kernel_launch(void* const* d_in, const int* in_sizes, int n_in,
                              void* d_out, int out_size)
{
    const float* x   = (const float*)d_in[0];
    const int*   ptr = (const int*)  d_in[1];
    const int*   idx = (const int*)  d_in[2];
    const int*   rel = (const int*)  d_in[3];
    const float* W1  = (const float*)d_in[4];   // [512][64]
    const float* W2  = (const float*)d_in[5];   // [512][40]
    float* out = (float*)d_out;

    const int n = in_sizes[1] - 1;

    float *agg, *h;
    cudaGetSymbolAddress((void**)&agg, g_agg);
    cudaGetSymbolAddress((void**)&h,   g_h);

    const int agg_grid  = (n + 7) / 8;
    const int gemm_grid = (n + 255) / 256;      // 293

    const int s1 = 32768 * 4 + 2 * 32 * 64 * 8;  // 163840
    const int s2 = 32768 * 4 + 2 * 32 * 40 * 8;  // 151552
    cudaFuncSetAttribute(gemm_kernel<64>, cudaFuncAttributeMaxDynamicSharedMemorySize, s1);
    cudaFuncSetAttribute(gemm_kernel<40>, cudaFuncAttributeMaxDynamicSharedMemorySize, s2);

    agg_kernel<<<agg_grid, 256>>>(x, ptr, idx, rel, agg, n);
    gemm_kernel<64><<<gemm_grid, 512, s1>>>(agg, W1, h, n);
    agg_kernel<<<agg_grid, 256>>>(h, ptr, idx, rel, agg, n);
    gemm_kernel<40><<<gemm_grid, 512, s2>>>(agg, W2, out, n);
}

// round 10
// speedup vs baseline: 1.2784x; 1.2784x over previous
#include <cuda_runtime.h>
#include <math.h>

typedef unsigned long long ull;
typedef unsigned int u32;

#define MAXN_PAD 75008   // 293 blocks * 256 rows

// Global scratch (static __device__ arrays: never allocated at runtime)
__device__ float g_agg[(size_t)MAXN_PAD * 512];   // 153.6 MB
__device__ float g_h  [(size_t)MAXN_PAD * 64];    // 19.2 MB

__device__ __forceinline__ void upk2(ull v, float& x, float& y) {
    asm("mov.b64 {%0, %1}, %2;" : "=f"(x), "=f"(y) : "l"(v));
}
__device__ __forceinline__ void ffma2(ull& d, ull a, ull b) {
    asm("fma.rn.f32x2 %0, %1, %2, %0;" : "+l"(d) : "l"(a), "l"(b));
}
__device__ __forceinline__ void fadd2(ull& d, ull a) {
    asm("add.rn.f32x2 %0, %0, %1;" : "+l"(d) : "l"(a));
}
__device__ __forceinline__ u32 smem_u32(const void* p) {
    u32 a;
    asm("{ .reg .u64 t; cvta.to.shared.u64 t, %1; cvt.u32.u64 %0, t; }" : "=r"(a) : "l"(p));
    return a;
}
__device__ __forceinline__ void cp16(u32 dst, const void* src) {
    asm volatile("cp.async.cg.shared.global [%0], [%1], 16;" :: "r"(dst), "l"(src));
}
__device__ __forceinline__ void cp_commit() { asm volatile("cp.async.commit_group;"); }
__device__ __forceinline__ void cp_wait1()  { asm volatile("cp.async.wait_group 1;"); }
__device__ __forceinline__ void cp_wait0()  { asm volatile("cp.async.wait_group 0;"); }

// ---------------------------------------------------------------------------
// Aggregation: one warp per node.  agg[node][r*64+d] = sum_{e: rel_e=r} x[src_e][d]
// Ballot per relation; within a relation the next edge's load is issued BEFORE
// the current fadd2 (software pipeline depth 2 -> one exposed L2 latency per
// relation instead of per edge).
// ---------------------------------------------------------------------------
__global__ void __launch_bounds__(256)
agg_kernel(const float* __restrict__ xin,
           const int*   __restrict__ ptr,
           const int*   __restrict__ idx,
           const int*   __restrict__ rel,
           float*       __restrict__ agg,
           int n)
{
    const int node = (blockIdx.x * blockDim.x + threadIdx.x) >> 5;
    const int lane = threadIdx.x & 31;
    if (node >= n) return;

    ull acc[8];
    #pragma unroll
    for (int r = 0; r < 8; ++r) acc[r] = 0ull;

    const int e0 = ptr[node], e1 = ptr[node + 1];
    for (int eb = e0; eb < e1; eb += 32) {
        const int cnt = min(32, e1 - eb);
        int mi = 0, mr = -1;
        if (lane < cnt) { mi = idx[eb + lane]; mr = rel[eb + lane]; }
        #pragma unroll
        for (int r = 0; r < 8; ++r) {
            unsigned m = __ballot_sync(0xffffffffu, mr == r);
            if (!m) continue;
            int t = __ffs(m) - 1; m &= m - 1;
            int s = __shfl_sync(0xffffffffu, mi, t);
            ull v = *(const ull*)(xin + (size_t)s * 64 + 2 * lane);
            while (m) {
                int t2 = __ffs(m) - 1; m &= m - 1;
                int s2 = __shfl_sync(0xffffffffu, mi, t2);
                ull v2 = *(const ull*)(xin + (size_t)s2 * 64 + 2 * lane);
                fadd2(acc[r], v);          // v in flight while v2 loads
                v = v2;
            }
            fadd2(acc[r], v);
        }
    }

    float* arow = agg + (size_t)node * 512;
    #pragma unroll
    for (int r = 0; r < 8; ++r)
        *(ull*)(arow + r * 64 + 2 * lane) = acc[r];
}

// ---------------------------------------------------------------------------
// GEMM layer 1: H[256 x 64] per block = relu(A[256 x 512] @ W[512 x 64])
//   256 threads = 8 warps; warp w owns 8 columns (broadcast B LDS.128).
//   lane owns rows {lane + 32j}, j=0..7; thread tile 8 x 8.
//   A SMEM: [2][256][64] floats, XOR swizzle c4^(row&7) (conflict-free).
//   B SMEM: [2][32][64] k-pair-packed ull; warp reads 4x ulonglong2 per kp2.
// ---------------------------------------------------------------------------
__global__ void __launch_bounds__(256, 1)
gemm1_kernel(const float* __restrict__ A,
             const float* __restrict__ W,    // [512][64]
             float*       __restrict__ out,  // g_h
             int n)
{
    extern __shared__ float sm[];
    float* As = sm;                          // [2][16384] floats
    ull*   Bs = (ull*)(sm + 32768);          // [2][32*64] ull
    const u32 asb = smem_u32(As);

    const int tid  = threadIdx.x;
    const int lane = tid & 31;
    const int w    = tid >> 5;
    const size_t row0 = (size_t)blockIdx.x * 256;

    auto cpA = [&](int ch, int buf) {
        #pragma unroll
        for (int i = 0; i < 16; ++i) {
            int v  = tid + i * 256;
            int r  = v >> 4, c4 = v & 15;
            u32 d = asb + (u32)((buf * 16384 + r * 64 + ((c4 ^ (r & 7)) << 2)) * 4);
            cp16(d, A + (row0 + r) * 512 + ch * 64 + c4 * 4);
        }
        cp_commit();
    };

    float2 br[8];
    auto ldgB = [&](int ch) {
        #pragma unroll
        for (int i = 0; i < 8; ++i) {
            int v = tid + i * 256;
            int kp = v >> 6, c = v & 63;
            const float* p = W + (size_t)(ch * 64 + 2 * kp) * 64 + c;
            br[i].x = p[0]; br[i].y = p[64];
        }
    };
    auto stsB = [&](int buf) {
        ull* bs = Bs + buf * 2048;
        #pragma unroll
        for (int i = 0; i < 8; ++i) {
            int v = tid + i * 256;
            int kp = v >> 6, c = v & 63;
            *(float2*)(bs + kp * 64 + c) = br[i];
        }
    };

    ull acc[8][8];
    #pragma unroll
    for (int j = 0; j < 8; ++j)
        #pragma unroll
        for (int c = 0; c < 8; ++c) acc[j][c] = 0ull;

    cpA(0, 0);
    cpA(1, 1);
    ldgB(0); stsB(0);

    #pragma unroll 1
    for (int ch = 0; ch < 8; ++ch) {
        const int buf = ch & 1;
        if (ch < 7) ldgB(ch + 1);
        if (ch == 7) cp_wait0(); else cp_wait1();
        __syncthreads();

        const float* as = As + buf * 16384 + lane * 64;
        const ull*   bs = Bs + buf * 2048 + w * 8;
        #pragma unroll
        for (int kp2 = 0; kp2 < 16; ++kp2) {
            ulonglong2 q;
            ull b0[8], b1[8];
            q = *(const ulonglong2*)(bs + (2 * kp2) * 64 + 0); b0[0]=q.x; b0[1]=q.y;
            q = *(const ulonglong2*)(bs + (2 * kp2) * 64 + 2); b0[2]=q.x; b0[3]=q.y;
            q = *(const ulonglong2*)(bs + (2 * kp2) * 64 + 4); b0[4]=q.x; b0[5]=q.y;
            q = *(const ulonglong2*)(bs + (2 * kp2) * 64 + 6); b0[6]=q.x; b0[7]=q.y;
            q = *(const ulonglong2*)(bs + (2 * kp2 + 1) * 64 + 0); b1[0]=q.x; b1[1]=q.y;
            q = *(const ulonglong2*)(bs + (2 * kp2 + 1) * 64 + 2); b1[2]=q.x; b1[3]=q.y;
            q = *(const ulonglong2*)(bs + (2 * kp2 + 1) * 64 + 4); b1[4]=q.x; b1[5]=q.y;
            q = *(const ulonglong2*)(bs + (2 * kp2 + 1) * 64 + 6); b1[6]=q.x; b1[7]=q.y;
            const int swoff = (kp2 ^ (lane & 7)) << 2;
            #pragma unroll
            for (int j = 0; j < 8; ++j) {
                ulonglong2 a = *(const ulonglong2*)(as + j * 2048 + swoff);
                #pragma unroll
                for (int c = 0; c < 8; ++c) {
                    ffma2(acc[j][c], a.x, b0[c]);
                    ffma2(acc[j][c], a.y, b1[c]);
                }
            }
        }
        __syncthreads();

        if (ch < 7) stsB((ch + 1) & 1);
        if (ch < 6) cpA(ch + 2, buf);
    }

    #pragma unroll
    for (int j = 0; j < 8; ++j) {
        size_t g = row0 + lane + 32 * j;
        float lo, hi; float4 o;
        upk2(acc[j][0], lo, hi); o.x = fmaxf(lo + hi, 0.f);
        upk2(acc[j][1], lo, hi); o.y = fmaxf(lo + hi, 0.f);
        upk2(acc[j][2], lo, hi); o.z = fmaxf(lo + hi, 0.f);
        upk2(acc[j][3], lo, hi); o.w = fmaxf(lo + hi, 0.f);
        *(float4*)(out + g * 64 + w * 8) = o;
        upk2(acc[j][4], lo, hi); o.x = fmaxf(lo + hi, 0.f);
        upk2(acc[j][5], lo, hi); o.y = fmaxf(lo + hi, 0.f);
        upk2(acc[j][6], lo, hi); o.z = fmaxf(lo + hi, 0.f);
        upk2(acc[j][7], lo, hi); o.w = fmaxf(lo + hi, 0.f);
        *(float4*)(out + g * 64 + w * 8 + 4) = o;
    }
}

// ---------------------------------------------------------------------------
// GEMM layer 2 + log_softmax: out[256 x 40] per block.
//   Warp w owns 5 columns. B SMEM padded [kp][48] ull (col-group stride 6,
//   16B aligned) -> 2x LDS.128 + 1x LDS.64 per kp.
// ---------------------------------------------------------------------------
__global__ void __launch_bounds__(256, 1)
gemm2_kernel(const float* __restrict__ A,
             const float* __restrict__ W,    // [512][40]
             float*       __restrict__ out,  // [n][40]
             int n)
{
    extern __shared__ float sm[];
    float* As = sm;                          // [2][16384] floats
    ull*   Bs = (ull*)(sm + 32768);          // [2][32*48] ull (padded)
    const u32 asb = smem_u32(As);

    const int tid  = threadIdx.x;
    const int lane = tid & 31;
    const int w    = tid >> 5;
    const size_t row0 = (size_t)blockIdx.x * 256;

    auto cpA = [&](int ch, int buf) {
        #pragma unroll
        for (int i = 0; i < 16; ++i) {
            int v  = tid + i * 256;
            int r  = v >> 4, c4 = v & 15;
            u32 d = asb + (u32)((buf * 16384 + r * 64 + ((c4 ^ (r & 7)) << 2)) * 4);
            cp16(d, A + (row0 + r) * 512 + ch * 64 + c4 * 4);
        }
        cp_commit();
    };

    float2 br[5];
    auto ldgB = [&](int ch) {
        #pragma unroll
        for (int i = 0; i < 5; ++i) {
            int v = tid + i * 256;           // < 1280
            int kp = v / 40, c = v % 40;
            const float* p = W + (size_t)(ch * 64 + 2 * kp) * 40 + c;
            br[i].x = p[0]; br[i].y = p[40];
        }
    };
    auto stsB = [&](int buf) {
        ull* bs = Bs + buf * 32 * 48;
        #pragma unroll
        for (int i = 0; i < 5; ++i) {
            int v = tid + i * 256;
            int kp = v / 40, c = v % 40;
            *(float2*)(bs + kp * 48 + (c / 5) * 6 + (c % 5)) = br[i];
        }
    };

    ull acc[8][5];
    #pragma unroll
    for (int j = 0; j < 8; ++j)
        #pragma unroll
        for (int c = 0; c < 5; ++c) acc[j][c] = 0ull;

    cpA(0, 0);
    cpA(1, 1);
    ldgB(0); stsB(0);

    #pragma unroll 1
    for (int ch = 0; ch < 8; ++ch) {
        const int buf = ch & 1;
        if (ch < 7) ldgB(ch + 1);
        if (ch == 7) cp_wait0(); else cp_wait1();
        __syncthreads();

        const float* as = As + buf * 16384 + lane * 64;
        const ull*   bs = Bs + buf * 32 * 48 + w * 6;
        #pragma unroll
        for (int kp2 = 0; kp2 < 16; ++kp2) {
            ull b0[5], b1[5];
            {
                const ull* p0 = bs + (2 * kp2) * 48;
                const ull* p1 = p0 + 48;
                ulonglong2 q;
                q = *(const ulonglong2*)(p0);     b0[0]=q.x; b0[1]=q.y;
                q = *(const ulonglong2*)(p0 + 2); b0[2]=q.x; b0[3]=q.y;
                b0[4] = p0[4];
                q = *(const ulonglong2*)(p1);     b1[0]=q.x; b1[1]=q.y;
                q = *(const ulonglong2*)(p1 + 2); b1[2]=q.x; b1[3]=q.y;
                b1[4] = p1[4];
            }
            const int swoff = (kp2 ^ (lane & 7)) << 2;
            #pragma unroll
            for (int j = 0; j < 8; ++j) {
                ulonglong2 a = *(const ulonglong2*)(as + j * 2048 + swoff);
                #pragma unroll
                for (int c = 0; c < 5; ++c) {
                    ffma2(acc[j][c], a.x, b0[c]);
                    ffma2(acc[j][c], a.y, b1[c]);
                }
            }
        }
        __syncthreads();

        if (ch < 7) stsB((ch + 1) & 1);
        if (ch < 6) cpA(ch + 2, buf);
    }

    // partials -> smem exchange (overlays As; all A reads done)
    __syncthreads();
    float* so = As;                           // [256][41]
    #pragma unroll
    for (int j = 0; j < 8; ++j)
        #pragma unroll
        for (int c = 0; c < 5; ++c) {
            float lo, hi; upk2(acc[j][c], lo, hi);
            so[(lane + 32 * j) * 41 + w * 5 + c] = lo + hi;
        }
    __syncthreads();

    {   // lane-per-row softmax: warp w handles rows w*32..w*32+31
        const int row = w * 32 + lane;
        float v[40];
        float m = -INFINITY;
        #pragma unroll
        for (int c = 0; c < 40; ++c) { v[c] = so[row * 41 + c]; m = fmaxf(m, v[c]); }
        float s = 0.f;
        #pragma unroll
        for (int c = 0; c < 40; ++c) s += expf(v[c] - m);
        float lse = m + logf(s);
        #pragma unroll
        for (int c = 0; c < 40; ++c) so[row * 41 + c] = v[c] - lse;
    }
    __syncthreads();

    // coalesced copy-out with n-guard
    const int total = (int)min((size_t)256, (size_t)n - row0) * 40;
    for (int e = tid; e < total; e += 256) {
        int r = e / 40, c = e % 40;
        out[row0 * 40 + e] = so[r * 41 + c];
    }
}

// ---------------------------------------------------------------------------
extern "C" void kernel_launch(void* const* d_in, const int* in_sizes, int n_in,
                              void* d_out, int out_size)
{
    const float* x   = (const float*)d_in[0];
    const int*   ptr = (const int*)  d_in[1];
    const int*   idx = (const int*)  d_in[2];
    const int*   rel = (const int*)  d_in[3];
    const float* W1  = (const float*)d_in[4];   // [512][64]
    const float* W2  = (const float*)d_in[5];   // [512][40]
    float* out = (float*)d_out;

    const int n = in_sizes[1] - 1;

    float *agg, *h;
    cudaGetSymbolAddress((void**)&agg, g_agg);
    cudaGetSymbolAddress((void**)&h,   g_h);

    const int agg_grid  = (n + 7) / 8;
    const int gemm_grid = (n + 255) / 256;      // 293

    const int s1 = 32768 * 4 + 2 * 2048 * 8;    // 163840
    const int s2 = 32768 * 4 + 2 * 32 * 48 * 8; // 155648
    cudaFuncSetAttribute(gemm1_kernel, cudaFuncAttributeMaxDynamicSharedMemorySize, s1);
    cudaFuncSetAttribute(gemm2_kernel, cudaFuncAttributeMaxDynamicSharedMemorySize, s2);

    agg_kernel<<<agg_grid, 256>>>(x, ptr, idx, rel, agg, n);
    gemm1_kernel<<<gemm_grid, 256, s1>>>(agg, W1, h, n);
    agg_kernel<<<agg_grid, 256>>>(h, ptr, idx, rel, agg, n);
    gemm2_kernel<<<gemm_grid, 256, s2>>>(agg, W2, out, n);
}

// round 11
// speedup vs baseline: 1.2869x; 1.0066x over previous
#include <cuda_runtime.h>
#include <math.h>

typedef unsigned long long ull;
typedef unsigned int u32;

#define MAXN_PAD 75008   // 293 blocks * 256 rows

// Global scratch (static __device__ arrays: never allocated at runtime)
__device__ float g_agg[(size_t)MAXN_PAD * 512];   // 153.6 MB
__device__ float g_h  [(size_t)MAXN_PAD * 64];    // 19.2 MB
__device__ ull   g_W1p[256 * 64];                 // W1 k-pair packed [kp][64]
__device__ ull   g_W2p[16 * 16 * 48];             // W2 packed [ch][kp][48] (pad 6/grp)

__device__ __forceinline__ ull pk2(float x, float y) {
    ull r; asm("mov.b64 %0, {%1, %2};" : "=l"(r) : "f"(x), "f"(y)); return r;
}
__device__ __forceinline__ void upk2(ull v, float& x, float& y) {
    asm("mov.b64 {%0, %1}, %2;" : "=f"(x), "=f"(y) : "l"(v));
}
__device__ __forceinline__ void ffma2(ull& d, ull a, ull b) {
    asm("fma.rn.f32x2 %0, %1, %2, %0;" : "+l"(d) : "l"(a), "l"(b));
}
__device__ __forceinline__ void fadd2(ull& d, ull a) {
    asm("add.rn.f32x2 %0, %0, %1;" : "+l"(d) : "l"(a));
}
__device__ __forceinline__ u32 smem_u32(const void* p) {
    u32 a;
    asm("{ .reg .u64 t; cvta.to.shared.u64 t, %1; cvt.u32.u64 %0, t; }" : "=r"(a) : "l"(p));
    return a;
}
__device__ __forceinline__ void cp16(u32 dst, const void* src) {
    asm volatile("cp.async.cg.shared.global [%0], [%1], 16;" :: "r"(dst), "l"(src));
}
__device__ __forceinline__ void cp_commit() { asm volatile("cp.async.commit_group;"); }
__device__ __forceinline__ void cp_wait0()  { asm volatile("cp.async.wait_group 0;"); }

// ---------------------------------------------------------------------------
// W prep: k-pair pack into the GEMM's SMEM layout (run once per call, ~2us)
// ---------------------------------------------------------------------------
__global__ void prep1_kernel(const float* __restrict__ W1, ull* __restrict__ Wp)
{
    int i = blockIdx.x * 256 + threadIdx.x;      // 16384 elems
    if (i < 256 * 64) {
        int kp = i >> 6, c = i & 63;
        Wp[i] = pk2(W1[(size_t)(2 * kp) * 64 + c], W1[(size_t)(2 * kp + 1) * 64 + c]);
    }
}
__global__ void prep2_kernel(const float* __restrict__ W2, ull* __restrict__ Wp)
{
    int i = blockIdx.x * 256 + threadIdx.x;      // 10240 elems
    if (i < 256 * 40) {
        int kp = i / 40, c = i % 40;
        int ch = kp >> 4, kl = kp & 15;
        Wp[ch * 768 + kl * 48 + (c / 5) * 6 + (c % 5)] =
            pk2(W2[(size_t)(2 * kp) * 40 + c], W2[(size_t)(2 * kp + 1) * 40 + c]);
    }
}

// ---------------------------------------------------------------------------
// Aggregation: one warp per node (pipelined ballot gather), unchanged from R10.
// ---------------------------------------------------------------------------
__global__ void __launch_bounds__(256)
agg_kernel(const float* __restrict__ xin,
           const int*   __restrict__ ptr,
           const int*   __restrict__ idx,
           const int*   __restrict__ rel,
           float*       __restrict__ agg,
           int n)
{
    const int node = (blockIdx.x * blockDim.x + threadIdx.x) >> 5;
    const int lane = threadIdx.x & 31;
    if (node >= n) return;

    ull acc[8];
    #pragma unroll
    for (int r = 0; r < 8; ++r) acc[r] = 0ull;

    const int e0 = ptr[node], e1 = ptr[node + 1];
    for (int eb = e0; eb < e1; eb += 32) {
        const int cnt = min(32, e1 - eb);
        int mi = 0, mr = -1;
        if (lane < cnt) { mi = idx[eb + lane]; mr = rel[eb + lane]; }
        #pragma unroll
        for (int r = 0; r < 8; ++r) {
            unsigned m = __ballot_sync(0xffffffffu, mr == r);
            if (!m) continue;
            int t = __ffs(m) - 1; m &= m - 1;
            int s = __shfl_sync(0xffffffffu, mi, t);
            ull v = *(const ull*)(xin + (size_t)s * 64 + 2 * lane);
            while (m) {
                int t2 = __ffs(m) - 1; m &= m - 1;
                int s2 = __shfl_sync(0xffffffffu, mi, t2);
                ull v2 = *(const ull*)(xin + (size_t)s2 * 64 + 2 * lane);
                fadd2(acc[r], v);
                v = v2;
            }
            fadd2(acc[r], v);
        }
    }

    float* arow = agg + (size_t)node * 512;
    #pragma unroll
    for (int r = 0; r < 8; ++r)
        *(ull*)(arow + r * 64 + 2 * lane) = acc[r];
}

// ---------------------------------------------------------------------------
// GEMM layer 1: H[256 x 64]/block = relu(A[256 x 512] @ W1), 8 chunks of K=64.
// 256 thr, 8 warps, tile 8x8. A+B both cp.async (one group/chunk, one sync).
// ---------------------------------------------------------------------------
__global__ void __launch_bounds__(256, 1)
gemm1_kernel(const float* __restrict__ A,
             const ull*   __restrict__ Wp,   // [256 kp][64] packed
             float*       __restrict__ out,  // g_h
             int n)
{
    extern __shared__ float sm[];
    float* As = sm;                          // [2][16384] floats
    ull*   Bs = (ull*)(sm + 32768);          // [2][2048] ull
    const u32 asb = smem_u32(As);
    const u32 bsb = smem_u32(Bs);

    const int tid  = threadIdx.x;
    const int lane = tid & 31;
    const int w    = tid >> 5;
    const size_t row0 = (size_t)blockIdx.x * 256;

    auto stage = [&](int ch, int buf) {
        #pragma unroll
        for (int i = 0; i < 16; ++i) {       // A: 4096 16B blocks
            int v  = tid + i * 256;
            int r  = v >> 4, c4 = v & 15;
            u32 d = asb + (u32)((buf * 16384 + r * 64 + ((c4 ^ (r & 7)) << 2)) * 4);
            cp16(d, A + (row0 + r) * 512 + ch * 64 + c4 * 4);
        }
        #pragma unroll
        for (int i = 0; i < 4; ++i) {        // B: 1024 16B blocks (contiguous)
            int v = tid + i * 256;
            cp16(bsb + (u32)((buf * 2048 + v * 2) * 8), Wp + (size_t)ch * 2048 + v * 2);
        }
        cp_commit();
    };

    ull acc[8][8];
    #pragma unroll
    for (int j = 0; j < 8; ++j)
        #pragma unroll
        for (int c = 0; c < 8; ++c) acc[j][c] = 0ull;

    stage(0, 0);

    #pragma unroll 1
    for (int ch = 0; ch < 8; ++ch) {
        const int buf = ch & 1;
        cp_wait0();
        __syncthreads();
        if (ch < 7) stage(ch + 1, buf ^ 1);

        const float* as = As + buf * 16384 + lane * 64;
        const ull*   bs = Bs + buf * 2048 + w * 8;
        #pragma unroll
        for (int kp2 = 0; kp2 < 16; ++kp2) {
            ulonglong2 q;
            ull b0[8], b1[8];
            q = *(const ulonglong2*)(bs + (2 * kp2) * 64 + 0); b0[0]=q.x; b0[1]=q.y;
            q = *(const ulonglong2*)(bs + (2 * kp2) * 64 + 2); b0[2]=q.x; b0[3]=q.y;
            q = *(const ulonglong2*)(bs + (2 * kp2) * 64 + 4); b0[4]=q.x; b0[5]=q.y;
            q = *(const ulonglong2*)(bs + (2 * kp2) * 64 + 6); b0[6]=q.x; b0[7]=q.y;
            q = *(const ulonglong2*)(bs + (2 * kp2 + 1) * 64 + 0); b1[0]=q.x; b1[1]=q.y;
            q = *(const ulonglong2*)(bs + (2 * kp2 + 1) * 64 + 2); b1[2]=q.x; b1[3]=q.y;
            q = *(const ulonglong2*)(bs + (2 * kp2 + 1) * 64 + 4); b1[4]=q.x; b1[5]=q.y;
            q = *(const ulonglong2*)(bs + (2 * kp2 + 1) * 64 + 6); b1[6]=q.x; b1[7]=q.y;
            const int swoff = (kp2 ^ (lane & 7)) << 2;
            #pragma unroll
            for (int j = 0; j < 8; ++j) {
                ulonglong2 a = *(const ulonglong2*)(as + j * 2048 + swoff);
                #pragma unroll
                for (int c = 0; c < 8; ++c) {
                    ffma2(acc[j][c], a.x, b0[c]);
                    ffma2(acc[j][c], a.y, b1[c]);
                }
            }
        }
    }

    #pragma unroll
    for (int j = 0; j < 8; ++j) {
        size_t g = row0 + lane + 32 * j;
        float lo, hi; float4 o;
        upk2(acc[j][0], lo, hi); o.x = fmaxf(lo + hi, 0.f);
        upk2(acc[j][1], lo, hi); o.y = fmaxf(lo + hi, 0.f);
        upk2(acc[j][2], lo, hi); o.z = fmaxf(lo + hi, 0.f);
        upk2(acc[j][3], lo, hi); o.w = fmaxf(lo + hi, 0.f);
        *(float4*)(out + g * 64 + w * 8) = o;
        upk2(acc[j][4], lo, hi); o.x = fmaxf(lo + hi, 0.f);
        upk2(acc[j][5], lo, hi); o.y = fmaxf(lo + hi, 0.f);
        upk2(acc[j][6], lo, hi); o.z = fmaxf(lo + hi, 0.f);
        upk2(acc[j][7], lo, hi); o.w = fmaxf(lo + hi, 0.f);
        *(float4*)(out + g * 64 + w * 8 + 4) = o;
    }
}

// ---------------------------------------------------------------------------
// GEMM layer 2 + log_softmax: out[256 x 40]/block, 16 chunks of K=32.
// 256 thr, 8 warps, tile 8x5, 2 CTAs/SM (reg cap 128, 76 KB SMEM).
// ---------------------------------------------------------------------------
__global__ void __launch_bounds__(256, 2)
gemm2_kernel(const float* __restrict__ A,
             const ull*   __restrict__ Wp,   // [16 ch][16 kp][48] packed
             float*       __restrict__ out,  // [n][40]
             int n)
{
    extern __shared__ float sm[];
    float* As = sm;                          // [2][8192] floats (K=32 chunks)
    ull*   Bs = (ull*)(sm + 16384);          // [2][768] ull
    const u32 asb = smem_u32(As);
    const u32 bsb = smem_u32(Bs);

    const int tid  = threadIdx.x;
    const int lane = tid & 31;
    const int w    = tid >> 5;
    const size_t row0 = (size_t)blockIdx.x * 256;

    auto stage = [&](int ch, int buf) {
        #pragma unroll
        for (int i = 0; i < 8; ++i) {        // A: 2048 16B blocks
            int v  = tid + i * 256;
            int r  = v >> 3, c4 = v & 7;
            u32 d = asb + (u32)((buf * 8192 + r * 32 + ((c4 ^ (r & 7)) << 2)) * 4);
            cp16(d, A + (row0 + r) * 512 + ch * 32 + c4 * 4);
        }
        #pragma unroll
        for (int i = 0; i < 2; ++i) {        // B: 384 16B blocks
            int v = tid + i * 256;
            if (v < 384)
                cp16(bsb + (u32)((buf * 768 + v * 2) * 8), Wp + (size_t)ch * 768 + v * 2);
        }
        cp_commit();
    };

    ull acc[8][5];
    #pragma unroll
    for (int j = 0; j < 8; ++j)
        #pragma unroll
        for (int c = 0; c < 5; ++c) acc[j][c] = 0ull;

    stage(0, 0);

    #pragma unroll 1
    for (int ch = 0; ch < 16; ++ch) {
        const int buf = ch & 1;
        cp_wait0();
        __syncthreads();
        if (ch < 15) stage(ch + 1, buf ^ 1);

        const float* as = As + buf * 8192 + lane * 32;
        const ull*   bs = Bs + buf * 768 + w * 6;
        #pragma unroll
        for (int kp2 = 0; kp2 < 8; ++kp2) {
            ull b0[5], b1[5];
            {
                const ull* p0 = bs + (2 * kp2) * 48;
                const ull* p1 = p0 + 48;
                ulonglong2 q;
                q = *(const ulonglong2*)(p0);     b0[0]=q.x; b0[1]=q.y;
                q = *(const ulonglong2*)(p0 + 2); b0[2]=q.x; b0[3]=q.y;
                b0[4] = p0[4];
                q = *(const ulonglong2*)(p1);     b1[0]=q.x; b1[1]=q.y;
                q = *(const ulonglong2*)(p1 + 2); b1[2]=q.x; b1[3]=q.y;
                b1[4] = p1[4];
            }
            const int swoff = (kp2 ^ (lane & 7)) << 2;
            #pragma unroll
            for (int j = 0; j < 8; ++j) {
                ulonglong2 a = *(const ulonglong2*)(as + j * 1024 + swoff);
                #pragma unroll
                for (int c = 0; c < 5; ++c) {
                    ffma2(acc[j][c], a.x, b0[c]);
                    ffma2(acc[j][c], a.y, b1[c]);
                }
            }
        }
    }

    // partials -> smem exchange (overlays As; all A reads done after sync)
    __syncthreads();
    float* so = As;                           // [256][41] = 41984 B <= 64 KB
    #pragma unroll
    for (int j = 0; j < 8; ++j)
        #pragma unroll
        for (int c = 0; c < 5; ++c) {
            float lo, hi; upk2(acc[j][c], lo, hi);
            so[(lane + 32 * j) * 41 + w * 5 + c] = lo + hi;
        }
    __syncthreads();

    {   // lane-per-row softmax: warp w handles rows w*32..w*32+31
        const int row = w * 32 + lane;
        float v[40];
        float m = -INFINITY;
        #pragma unroll
        for (int c = 0; c < 40; ++c) { v[c] = so[row * 41 + c]; m = fmaxf(m, v[c]); }
        float s = 0.f;
        #pragma unroll
        for (int c = 0; c < 40; ++c) s += expf(v[c] - m);
        float lse = m + logf(s);
        #pragma unroll
        for (int c = 0; c < 40; ++c) so[row * 41 + c] = v[c] - lse;
    }
    __syncthreads();

    // coalesced copy-out with n-guard
    const int total = (int)min((size_t)256, (size_t)n - row0) * 40;
    for (int e = tid; e < total; e += 256) {
        int r = e / 40, c = e % 40;
        out[row0 * 40 + e] = so[r * 41 + c];
    }
}

// ---------------------------------------------------------------------------
extern "C" void kernel_launch(void* const* d_in, const int* in_sizes, int n_in,
                              void* d_out, int out_size)
{
    const float* x   = (const float*)d_in[0];
    const int*   ptr = (const int*)  d_in[1];
    const int*   idx = (const int*)  d_in[2];
    const int*   rel = (const int*)  d_in[3];
    const float* W1  = (const float*)d_in[4];   // [512][64]
    const float* W2  = (const float*)d_in[5];   // [512][40]
    float* out = (float*)d_out;

    const int n = in_sizes[1] - 1;

    float *agg, *h;
    ull *w1p, *w2p;
    cudaGetSymbolAddress((void**)&agg, g_agg);
    cudaGetSymbolAddress((void**)&h,   g_h);
    cudaGetSymbolAddress((void**)&w1p, g_W1p);
    cudaGetSymbolAddress((void**)&w2p, g_W2p);

    const int agg_grid  = (n + 7) / 8;
    const int gemm_grid = (n + 255) / 256;      // 293

    const int s1 = 32768 * 4 + 2 * 2048 * 8;    // 163840
    const int s2 = 16384 * 4 + 2 * 768 * 8;     //  77824
    cudaFuncSetAttribute(gemm1_kernel, cudaFuncAttributeMaxDynamicSharedMemorySize, s1);
    cudaFuncSetAttribute(gemm2_kernel, cudaFuncAttributeMaxDynamicSharedMemorySize, s2);

    prep1_kernel<<<64, 256>>>(W1, w1p);
    prep2_kernel<<<40, 256>>>(W2, w2p);
    agg_kernel<<<agg_grid, 256>>>(x, ptr, idx, rel, agg, n);
    gemm1_kernel<<<gemm_grid, 256, s1>>>(agg, w1p, h, n);
    agg_kernel<<<agg_grid, 256>>>(h, ptr, idx, rel, agg, n);
    gemm2_kernel<<<gemm_grid, 256, s2>>>(agg, w2p, out, n);
}